// round 7
// baseline (speedup 1.0000x reference)
#include <cuda_runtime.h>

// BoxBlur 13x13 reflect, (8,64,512,512) fp32. Separable, sliding-window.
// = round-3 winner (192us) with ONE change: pass 2 stores float4 directly to
//   gmem (8 rows x 128B per warp = optimal wavefronts) -> staging smem, flush
//   loop, and 3 of 4 __syncthreads deleted.

#define Wd 512
#define Hd 512
#define TY 16
#define NT 512
#define PW 513            // vs stride (conflict-free row-strided access)
#define KHALF 6

#define SMEM_BYTES (TY * PW * 4)        // 32,832 B -> 3 CTAs/SM (reg-bound)

__device__ __forceinline__ int reflect_i(int i, int n) {
    // jnp.pad 'reflect', pad (6) < n: single fold.
    if (i < 0) i = -i;
    if (i >= n) i = 2 * n - 2 - i;
    return i;
}

__global__ __launch_bounds__(NT, 3)
void boxblur7(const float* __restrict__ in,
              const float* __restrict__ kern,
              float* __restrict__ out) {
    extern __shared__ float sm[];
    float* __restrict__ vs = sm;             // [TY][PW] vertical 13-sums

    const int ytile = blockIdx.x;
    const int plane = blockIdx.y;
    const int y0 = ytile * TY;
    const float* __restrict__ ip = in  + (size_t)plane * (Hd * Wd);
    float*       __restrict__ op = out + (size_t)plane * (Hd * Wd);
    const int t = threadIdx.x;               // 0..511
    const float k0 = kern[0];                // 1/169

    // ---- Pass 1: vertical running 13-sum, thread t = column t ----
    // (reload form: outgoing row re-read hits L1/L2; keeps regs under the
    //  occupancy-3 cap — a register ring spills here, see R6 post-mortem)
    {
        float s = 0.0f;
        #pragma unroll
        for (int j = -KHALF; j < KHALF; j++)           // 12 init rows
            s += ip[reflect_i(y0 + j, Hd) * Wd + t];
        #pragma unroll
        for (int j = 0; j < TY; j++) {
            s += ip[reflect_i(y0 + j + KHALF, Hd) * Wd + t];   // incoming
            vs[j * PW + t] = s;
            s -= ip[reflect_i(y0 + j - KHALF, Hd) * Wd + t];   // outgoing (cache hit)
        }
    }
    __syncthreads();

    // ---- Pass 2: horizontal sliding 13-sums, direct float4 STG ----
    const int rl  = t & 7;          // local row within half
    const int seg = t >> 3;         // 0..63, 8-wide x segment
    const int xb  = seg * 8;

    #pragma unroll
    for (int h = 0; h < 2; h++) {
        const int row = h * 8 + rl;
        const float* __restrict__ vrow = vs + row * PW;
        float* __restrict__ orow = op + (size_t)(y0 + row) * Wd;

        float ring[13];
        float s = 0.0f;
        #pragma unroll
        for (int k = 0; k < 13; k++) {
            const float v = vrow[reflect_i(xb - KHALF + k, Wd)];
            ring[k] = v;
            s += v;
        }
        float4 acc;
        #pragma unroll
        for (int i = 0; i < 8; i++) {
            const float o = s * k0;
            if ((i & 3) == 0)      acc.x = o;
            else if ((i & 3) == 1) acc.y = o;
            else if ((i & 3) == 2) acc.z = o;
            else {
                acc.w = o;
                // warp = 8 rows x 128B contiguous: optimal store wavefronts
                *(float4*)&orow[xb + i - 3] = acc;      // STG.128
            }
            const float v = vrow[reflect_i(xb + i + KHALF + 1, Wd)];
            s += v - ring[i];
            ring[i] = v;
        }
    }
}

extern "C" void kernel_launch(void* const* d_in, const int* in_sizes, int n_in,
                              void* d_out, int out_size) {
    const float* input  = (const float*)d_in[0];   // (8,64,512,512) fp32
    const float* kernel = (const float*)d_in[1];   // (1,13,13) fp32 uniform
    float* out = (float*)d_out;

    cudaFuncSetAttribute(boxblur7, cudaFuncAttributeMaxDynamicSharedMemorySize,
                         SMEM_BYTES);

    dim3 grid(Hd / TY, 8 * 64);    // (32 y-tiles, 512 planes)
    boxblur7<<<grid, NT, SMEM_BYTES>>>(input, kernel, out);
}

// round 8
// speedup vs baseline: 1.4390x; 1.4390x over previous
#include <cuda_runtime.h>

// BoxBlur 13x13 reflect, (8,64,512,512) fp32. Separable, sliding-window.
// Round-3 skeleton, but pass 2 is RING-FREE (smem reload) so register demand
// (~20) sits far below the occupancy-3 cap (42) -> no spill (R6/R7 killer).
// Direct float4 stores (no staging smem, 1 sync total).

#define Wd 512
#define Hd 512
#define TY 16
#define NT 512
#define PW 513            // vs stride: bank = (rl + 16*seg + c) % 32 -> conflict-free
#define KHALF 6

#define SMEM_BYTES (TY * PW * 4)        // 32,832 B -> 3 CTAs/SM

__device__ __forceinline__ int reflect_i(int i, int n) {
    // jnp.pad 'reflect', pad (6) < n: single fold.
    if (i < 0) i = -i;
    if (i >= n) i = 2 * n - 2 - i;
    return i;
}

__global__ __launch_bounds__(NT, 3)
void boxblur8(const float* __restrict__ in,
              const float* __restrict__ kern,
              float* __restrict__ out) {
    extern __shared__ float sm[];
    float* __restrict__ vs = sm;             // [TY][PW] vertical 13-sums

    const int ytile = blockIdx.x;
    const int plane = blockIdx.y;
    const int y0 = ytile * TY;
    const float* __restrict__ ip = in  + (size_t)plane * (Hd * Wd);
    float*       __restrict__ op = out + (size_t)plane * (Hd * Wd);
    const int t = threadIdx.x;               // 0..511
    const float k0 = kern[0];                // 1/169

    // ---- Pass 1: vertical running 13-sum, thread t = column t (reload form,
    //      low regs; outgoing-row re-read hits L1/L2) ----
    {
        float s = 0.0f;
        #pragma unroll
        for (int j = -KHALF; j < KHALF; j++)           // 12 init rows
            s += ip[reflect_i(y0 + j, Hd) * Wd + t];
        #pragma unroll
        for (int j = 0; j < TY; j++) {
            s += ip[reflect_i(y0 + j + KHALF, Hd) * Wd + t];   // incoming
            vs[j * PW + t] = s;
            s -= ip[reflect_i(y0 + j - KHALF, Hd) * Wd + t];   // outgoing (cache hit)
        }
    }
    __syncthreads();

    // ---- Pass 2: horizontal sliding 13-sum, ring-free (smem reload),
    //      16-wide segment per thread, direct float4 stores ----
    {
        const int rl  = t & 15;         // row 0..15
        const int seg = t >> 4;         // 0..31
        const int xb  = seg * 16;
        const float* __restrict__ vrow = vs + rl * PW;
        float* __restrict__ orow = op + (size_t)(y0 + rl) * Wd;

        float s = 0.0f;
        #pragma unroll
        for (int k = 0; k < 13; k++)
            s += vrow[reflect_i(xb - KHALF + k, Wd)];

        float4 acc;
        #pragma unroll
        for (int i = 0; i < 16; i++) {
            const float o = s * k0;
            if ((i & 3) == 0)      acc.x = o;
            else if ((i & 3) == 1) acc.y = o;
            else if ((i & 3) == 2) acc.z = o;
            else {
                acc.w = o;
                // per warp: 16 rows x 2 segs; both 16B pieces per row fall in
                // one 128B window -> 16 wavefronts/instr (no scatter blowup)
                *(float4*)&orow[xb + i - 3] = acc;      // STG.128, 32B-aligned
            }
            // slide: incoming x+7, outgoing x-6 (both conflict-free LDS)
            s += vrow[reflect_i(xb + i + KHALF + 1, Wd)]
               - vrow[reflect_i(xb + i - KHALF, Wd)];
        }
    }
}

extern "C" void kernel_launch(void* const* d_in, const int* in_sizes, int n_in,
                              void* d_out, int out_size) {
    const float* input  = (const float*)d_in[0];   // (8,64,512,512) fp32
    const float* kernel = (const float*)d_in[1];   // (1,13,13) fp32 uniform
    float* out = (float*)d_out;

    cudaFuncSetAttribute(boxblur8, cudaFuncAttributeMaxDynamicSharedMemorySize,
                         SMEM_BYTES);

    dim3 grid(Hd / TY, 8 * 64);    // (32 y-tiles, 512 planes)
    boxblur8<<<grid, NT, SMEM_BYTES>>>(input, kernel, out);
}